// round 6
// baseline (speedup 1.0000x reference)
#include <cuda_runtime.h>
#include <cuda_bf16.h>
#include <cstdint>

#define BATCH 16
#define NTOK  4096
#define CDIM  512
#define JDIM  64
#define ROWS  (BATCH*NTOK)   // 65536
#define NCHUNK 256           // 256-row softmax chunks (16 per batch)

// ---------- scratch (device globals; no runtime allocation) ----------
__device__ __nv_bfloat16 g_Wbf[JDIM*CDIM];   // fused w1@m0, [j][c]
__device__ float         g_blog[JDIM];       // b1@m0
__device__ __nv_bfloat16 g_Mbf[CDIM*JDIM];   // fused m1@w2, [c][j]
__device__ float         g_bns[CDIM], g_bnt[CDIM];
// logits, bf16, MMA-fragment order: [row/32 block][lane][32 u32]
__device__ uint32_t      g_logbf[2048*32*32];            // 8 MiB
__device__ float         g_pmax[NCHUNK*JDIM], g_psum[NCHUNK*JDIM];

// ---------- helpers ----------
__device__ __forceinline__ uint32_t packbf(float x, float y) {
    __nv_bfloat162 h = __floats2bfloat162_rn(x, y);
    return *reinterpret_cast<uint32_t*>(&h);
}
__device__ __forceinline__ float rt_bf(float x) {
    return __bfloat162float(__float2bfloat16_rn(x));
}
__device__ __forceinline__ void pfL2(const void* p) {
    asm volatile("prefetch.global.L2 [%0];" :: "l"(p));
}
__device__ __forceinline__ void mma16816(float* c, const uint32_t* a, const uint32_t* b) {
    asm volatile(
        "mma.sync.aligned.m16n8k16.row.col.f32.bf16.bf16.f32 "
        "{%0,%1,%2,%3},{%4,%5,%6,%7},{%8,%9},{%0,%1,%2,%3};"
        : "+f"(c[0]), "+f"(c[1]), "+f"(c[2]), "+f"(c[3])
        : "r"(a[0]), "r"(a[1]), "r"(a[2]), "r"(a[3]), "r"(b[0]), "r"(b[1]));
}

// ---------- K0: fold weights — smem-tiled, non-redundant ----------
// blocks [0,64):  W tile: 8 c-rows (c0=blk*8) x 64 j.  W[c][j]=sum_q w1[c][q]m0[q][j]
// blocks [64,128): M tile: 8 j-rows x 64 c.            M[j][c]=sum_q m1[j][q]w2[q][c]
// block 128: BN scale/shift + blog
__global__ __launch_bounds__(256) void k_fuse(const float* __restrict__ w1, const float* __restrict__ b1,
                       const float* __restrict__ m0, const float* __restrict__ m1,
                       const float* __restrict__ w2, const float* __restrict__ gamma,
                       const float* __restrict__ beta, const float* __restrict__ bmean,
                       const float* __restrict__ bvar) {
    __shared__ __align__(16) float s_stage[128*64]; // 32KB chunk: [128 q][64]
    __shared__ __align__(16) float s_rows[8*128];   // 4KB: [8 rows][128 q]
    __shared__ float s_red[4][64];

    int blk = blockIdx.x, tid = threadIdx.x;
    int co = tid >> 5, lx = tid & 31;

    if (blk < 64) {
        int c0 = blk * 8;
        float a0 = 0.f, a1 = 0.f;
        for (int ch = 0; ch < 4; ch++) {
            __syncthreads();
            // stage m0 chunk [128 q][64 j] — contiguous
            const float4* src4 = reinterpret_cast<const float4*>(m0 + ch*128*JDIM);
            float4* dst4 = reinterpret_cast<float4*>(s_stage);
            for (int i = tid; i < 2048; i += 256) dst4[i] = src4[i];
            // stage w1 rows [8 c][128 q]
            for (int i = tid; i < 1024; i += 256) {
                int coi = i >> 7, q = i & 127;
                s_rows[coi*128 + q] = w1[(size_t)(c0 + coi)*CDIM + ch*128 + q];
            }
            __syncthreads();
            #pragma unroll 8
            for (int q = 0; q < 128; q++) {
                float wv = s_rows[co*128 + q];
                float2 mv = *reinterpret_cast<const float2*>(&s_stage[q*64 + lx*2]);
                a0 = fmaf(wv, mv.x, a0);
                a1 = fmaf(wv, mv.y, a1);
            }
        }
        g_Wbf[(lx*2    )*CDIM + c0 + co] = __float2bfloat16_rn(a0);
        g_Wbf[(lx*2 + 1)*CDIM + c0 + co] = __float2bfloat16_rn(a1);
    } else if (blk < 128) {
        int i = blk - 64;
        int j0 = (i >> 3) * 8, c0 = (i & 7) * 64;
        float a0 = 0.f, a1 = 0.f;
        for (int ch = 0; ch < 4; ch++) {
            __syncthreads();
            // stage w2 chunk [128 q][64 c]
            float2* dst2 = reinterpret_cast<float2*>(s_stage);
            for (int i2 = tid; i2 < 4096; i2 += 256) {
                int q = i2 >> 5, c2 = i2 & 31;
                dst2[q*32 + c2] = *reinterpret_cast<const float2*>(
                    w2 + (size_t)(ch*128 + q)*CDIM + c0 + c2*2);
            }
            // stage m1 rows [8 j][128 q]
            for (int ii = tid; ii < 1024; ii += 256) {
                int coi = ii >> 7, q = ii & 127;
                s_rows[coi*128 + q] = m1[(size_t)(j0 + coi)*CDIM + ch*128 + q];
            }
            __syncthreads();
            #pragma unroll 8
            for (int q = 0; q < 128; q++) {
                float u = s_rows[co*128 + q];
                float2 wv = *reinterpret_cast<const float2*>(&s_stage[q*64 + lx*2]);
                a0 = fmaf(u, wv.x, a0);
                a1 = fmaf(u, wv.y, a1);
            }
        }
        g_Mbf[(c0 + lx*2    )*JDIM + j0 + co] = __float2bfloat16_rn(a0);
        g_Mbf[(c0 + lx*2 + 1)*JDIM + j0 + co] = __float2bfloat16_rn(a1);
    } else {
        // BN scale/shift
        for (int c = tid; c < CDIM; c += 256) {
            float s = gamma[c] * rsqrtf(bvar[c] + 1e-3f);
            g_bns[c] = s;
            g_bnt[c] = beta[c] - bmean[c] * s;
        }
        // blog[j] = b1 @ m0[:, j]
        int ks = tid >> 6, l6 = tid & 63;
        float aa = 0.f;
        #pragma unroll 4
        for (int q = 0; q < 128; q++)
            aa = fmaf(b1[ks*128 + q], m0[(size_t)(ks*128 + q)*JDIM + l6], aa);
        s_red[ks][l6] = aa;
        __syncthreads();
        if (tid < 64)
            g_blog[tid] = (s_red[0][tid] + s_red[1][tid]) + (s_red[2][tid] + s_red[3][tid]);
    }
}

// ---------- K1: logits = inputs @ W + blog; bf16 fragment store; fused stats ----
#define SMEM_LOGITS (64*260*4 + 64*4 + 8*64*4 + 64*4)   // 69120 B

__global__ __launch_bounds__(256) void k_logits(const float* __restrict__ in) {
    extern __shared__ __align__(16) unsigned char dyn_smem[];
    uint32_t* sw32  = reinterpret_cast<uint32_t*>(dyn_smem);          // [64][260] u32
    float*    sblog = reinterpret_cast<float*>(dyn_smem + 64*260*4);  // [64]
    float*    s_red = sblog + 64;                                     // [8][64]
    float*    s_cmx = s_red + 8*64;                                   // [64]

    int tid = threadIdx.x;
    const uint32_t* gw = reinterpret_cast<const uint32_t*>(g_Wbf); // 256 words/row
    for (int i = tid; i < 64*256; i += 256) {
        int j = i >> 8, w = i & 255;
        sw32[j*260 + w] = gw[i];
    }
    if (tid < JDIM) sblog[tid] = g_blog[tid];
    __syncthreads();

    int warp = tid >> 5, lane = tid & 31;
    int qr = lane >> 2, qc = lane & 3;
    int rowbase = blockIdx.x * 256 + warp * 32;

    float acc[2][8][4];
    #pragma unroll
    for (int nt = 0; nt < 8; nt++) {
        float b0 = sblog[nt*8 + qc*2], b1v = sblog[nt*8 + qc*2 + 1];
        #pragma unroll
        for (int s = 0; s < 2; s++) {
            acc[s][nt][0] = b0; acc[s][nt][1] = b1v;
            acc[s][nt][2] = b0; acc[s][nt][3] = b1v;
        }
    }

    const float* abase = in + (size_t)(rowbase + qr) * CDIM + qc*2;

    #pragma unroll 2
    for (int kk = 0; kk < 512; kk += 16) {
        // L2 prefetch: 4 rows per lane, 128 floats (512B) ahead, stay in-row
        if ((kk & 31) == 0 && kk < 384) {
            const float* pf = abase + kk + 128;
            pfL2(pf);
            pfL2(pf + 8*CDIM);
            pfL2(pf + 16*CDIM);
            pfL2(pf + 24*CDIM);
        }
        uint32_t a[2][4];
        #pragma unroll
        for (int s = 0; s < 2; s++) {
            const float* p = abase + s*16*CDIM + kk;
            float2 v0 = *reinterpret_cast<const float2*>(p);
            float2 v1 = *reinterpret_cast<const float2*>(p + 8*CDIM);
            float2 v2 = *reinterpret_cast<const float2*>(p + 8);
            float2 v3 = *reinterpret_cast<const float2*>(p + 8*CDIM + 8);
            a[s][0] = packbf(v0.x, v0.y); a[s][1] = packbf(v1.x, v1.y);
            a[s][2] = packbf(v2.x, v2.y); a[s][3] = packbf(v3.x, v3.y);
        }
        int bofs = (kk >> 1) + qc;
        #pragma unroll
        for (int nt = 0; nt < 8; nt++) {
            int n = nt*8 + qr;
            uint32_t b[2];
            b[0] = sw32[n*260 + bofs];
            b[1] = sw32[n*260 + bofs + 4];
            mma16816(acc[0][nt], a[0], b);
            mma16816(acc[1][nt], a[1], b);
        }
    }

    // ---- store logits in bf16 fragment order: 128B contiguous per lane ----
    {
        uint32_t vals[32];
        #pragma unroll
        for (int t = 0; t < 4; t++)
            #pragma unroll
            for (int s = 0; s < 2; s++) {
                int i0 = t*8 + s*4;
                vals[i0+0] = packbf(acc[s][2*t  ][0], acc[s][2*t  ][1]);
                vals[i0+1] = packbf(acc[s][2*t  ][2], acc[s][2*t  ][3]);
                vals[i0+2] = packbf(acc[s][2*t+1][0], acc[s][2*t+1][1]);
                vals[i0+3] = packbf(acc[s][2*t+1][2], acc[s][2*t+1][3]);
            }
        uint4* dst = reinterpret_cast<uint4*>(
            g_logbf + ((size_t)(blockIdx.x*8 + warp))*1024 + lane*32);
        #pragma unroll
        for (int v = 0; v < 8; v++)
            dst[v] = *reinterpret_cast<uint4*>(&vals[v*4]);
    }

    // ---- fused softmax stats over this CTA's 256 rows (bf16-rounded) ----
    #pragma unroll
    for (int nt = 0; nt < 8; nt++) {
        #pragma unroll
        for (int h = 0; h < 2; h++) {
            float v = fmaxf(fmaxf(rt_bf(acc[0][nt][h]), rt_bf(acc[0][nt][h+2])),
                            fmaxf(rt_bf(acc[1][nt][h]), rt_bf(acc[1][nt][h+2])));
            v = fmaxf(v, __shfl_xor_sync(0xffffffffu, v, 4));
            v = fmaxf(v, __shfl_xor_sync(0xffffffffu, v, 8));
            v = fmaxf(v, __shfl_xor_sync(0xffffffffu, v, 16));
            if (lane < 4) s_red[warp*64 + nt*8 + qc*2 + h] = v;
        }
    }
    __syncthreads();
    if (tid < 64) {
        float m = s_red[tid];
        #pragma unroll
        for (int w = 1; w < 8; w++) m = fmaxf(m, s_red[w*64 + tid]);
        s_cmx[tid] = m;
    }
    __syncthreads();
    #pragma unroll
    for (int nt = 0; nt < 8; nt++) {
        #pragma unroll
        for (int h = 0; h < 2; h++) {
            float cm = s_cmx[nt*8 + qc*2 + h];
            float v = __expf(rt_bf(acc[0][nt][h]) - cm) + __expf(rt_bf(acc[0][nt][h+2]) - cm)
                    + __expf(rt_bf(acc[1][nt][h]) - cm) + __expf(rt_bf(acc[1][nt][h+2]) - cm);
            v += __shfl_xor_sync(0xffffffffu, v, 4);
            v += __shfl_xor_sync(0xffffffffu, v, 8);
            v += __shfl_xor_sync(0xffffffffu, v, 16);
            if (lane < 4) s_red[warp*64 + nt*8 + qc*2 + h] = v;
        }
    }
    __syncthreads();
    if (tid < 64) {
        float s = 0.f;
        #pragma unroll
        for (int w = 0; w < 8; w++) s += s_red[w*64 + tid];
        g_pmax[blockIdx.x*JDIM + tid] = s_cmx[tid];
        g_psum[blockIdx.x*JDIM + tid] = s;
    }
}

// ---------- K2: out = relu( BN( (exp(logits-max)*inv) @ M ) + inputs ) ----------
__global__ __launch_bounds__(256) void k_out(const float* __restrict__ in,
                                             float* __restrict__ out) {
    __shared__ __align__(16) __nv_bfloat16 sM[128 * 72];
    __shared__ float s_s[128], s_t[128], s_mx[64], s_iv[64];

    int tid = threadIdx.x;
    int mt = blockIdx.x, nt4 = blockIdx.y;
    int cbase = nt4 * 128;
    int b = mt >> 5;

    int warp = tid >> 5, lane = tid & 31;
    int wm = warp & 3, wn = warp >> 2;
    int rowbase = mt*128 + wm*32;

    // L2 prefetch: residual lines this warp will read + its logits line.
    {
        const float* rp = in + (size_t)(rowbase + lane)*CDIM + cbase + wn*64;
        pfL2(rp);
        pfL2(rp + 32);
        pfL2(g_logbf + ((size_t)(mt*4 + wm))*1024 + lane*32);
    }

    uint32_t* sm32 = reinterpret_cast<uint32_t*>(sM);
    const uint32_t* gm = reinterpret_cast<const uint32_t*>(g_Mbf) + cbase*32;
    for (int i = tid; i < 128*32; i += 256) {
        int c = i >> 5, w = i & 31;
        sm32[c*36 + w] = gm[i];
    }
    if (tid < 128) { s_s[tid] = g_bns[cbase + tid]; s_t[tid] = g_bnt[cbase + tid]; }
    if (tid < 64) {
        float pm[16];
        float gmx = -1e30f;
        #pragma unroll
        for (int ch = 0; ch < 16; ch++) {
            pm[ch] = g_pmax[(b*16 + ch)*JDIM + tid];
            gmx = fmaxf(gmx, pm[ch]);
        }
        float Z = 0.f;
        #pragma unroll
        for (int ch = 0; ch < 16; ch++)
            Z += g_psum[(b*16 + ch)*JDIM + tid] * __expf(pm[ch] - gmx);
        s_mx[tid] = gmx;
        s_iv[tid] = 1.f / (Z * (1.f + 1e-9f));
    }
    __syncthreads();

    int qr = lane >> 2, qc = lane & 3;

    float acc[2][8][4];
    #pragma unroll
    for (int s = 0; s < 2; s++)
        #pragma unroll
        for (int nt = 0; nt < 8; nt++)
            #pragma unroll
            for (int r = 0; r < 4; r++) acc[s][nt][r] = 0.f;

    const uint4* lgb = reinterpret_cast<const uint4*>(
        g_logbf + ((size_t)(mt*4 + wm))*1024 + lane*32);

    #pragma unroll
    for (int t = 0; t < 4; t++) {
        int jj = t * 16;
        int j0 = jj + qc*2;
        float mA = s_mx[j0],   mB = s_mx[j0+1], iA = s_iv[j0],   iB = s_iv[j0+1];
        float mC = s_mx[j0+8], mD = s_mx[j0+9], iC = s_iv[j0+8], iD = s_iv[j0+9];
        uint32_t a[2][4];
        #pragma unroll
        for (int s = 0; s < 2; s++) {
            uint4 v = lgb[t*2 + s];
            float2 f0 = __bfloat1622float2(*reinterpret_cast<__nv_bfloat162*>(&v.x));
            float2 f1 = __bfloat1622float2(*reinterpret_cast<__nv_bfloat162*>(&v.y));
            float2 f2 = __bfloat1622float2(*reinterpret_cast<__nv_bfloat162*>(&v.z));
            float2 f3 = __bfloat1622float2(*reinterpret_cast<__nv_bfloat162*>(&v.w));
            a[s][0] = packbf(__expf(f0.x - mA)*iA, __expf(f0.y - mB)*iB);
            a[s][1] = packbf(__expf(f1.x - mA)*iA, __expf(f1.y - mB)*iB);
            a[s][2] = packbf(__expf(f2.x - mC)*iC, __expf(f2.y - mD)*iD);
            a[s][3] = packbf(__expf(f3.x - mC)*iC, __expf(f3.y - mD)*iD);
        }
        int bofs = (jj >> 1) + qc;
        #pragma unroll
        for (int nt = 0; nt < 8; nt++) {
            int cl = wn*64 + nt*8 + qr;
            uint32_t bb[2] = { sm32[cl*36 + bofs], sm32[cl*36 + bofs + 4] };
            mma16816(acc[0][nt], a[0], bb);
            mma16816(acc[1][nt], a[1], bb);
        }
    }

    #pragma unroll
    for (int s = 0; s < 2; s++)
        #pragma unroll
        for (int nt = 0; nt < 8; nt++) {
            int row = rowbase + s*16 + qr;
            int cl  = wn*64 + nt*8 + qc*2;
            int col = cbase + cl;
            float2 r0 = *reinterpret_cast<const float2*>(&in[(size_t)row*CDIM + col]);
            float2 r1 = *reinterpret_cast<const float2*>(&in[(size_t)(row + 8)*CDIM + col]);
            float2 o0, o1;
            o0.x = fmaxf(fmaf(acc[s][nt][0], s_s[cl],   s_t[cl])   + r0.x, 0.f);
            o0.y = fmaxf(fmaf(acc[s][nt][1], s_s[cl+1], s_t[cl+1]) + r0.y, 0.f);
            o1.x = fmaxf(fmaf(acc[s][nt][2], s_s[cl],   s_t[cl])   + r1.x, 0.f);
            o1.y = fmaxf(fmaf(acc[s][nt][3], s_s[cl+1], s_t[cl+1]) + r1.y, 0.f);
            *reinterpret_cast<float2*>(&out[(size_t)row*CDIM + col]) = o0;
            *reinterpret_cast<float2*>(&out[(size_t)(row + 8)*CDIM + col]) = o1;
        }
}

// ---------- launch ----------
extern "C" void kernel_launch(void* const* d_in, const int* in_sizes, int n_in,
                              void* d_out, int out_size) {
    (void)in_sizes; (void)n_in; (void)out_size;
    const float* inputs = (const float*)d_in[0];
    const float* w1     = (const float*)d_in[1];
    const float* b1     = (const float*)d_in[2];
    const float* m0     = (const float*)d_in[3];
    const float* m1     = (const float*)d_in[4];
    const float* w2     = (const float*)d_in[5];
    const float* gamma  = (const float*)d_in[6];
    const float* beta   = (const float*)d_in[7];
    const float* bmean  = (const float*)d_in[8];
    const float* bvar   = (const float*)d_in[9];

    static bool attr_done = false;
    if (!attr_done) {
        cudaFuncSetAttribute(k_logits, cudaFuncAttributeMaxDynamicSharedMemorySize,
                             SMEM_LOGITS);
        attr_done = true;
    }

    k_fuse<<<129, 256>>>(w1, b1, m0, m1, w2, gamma, beta, bmean, bvar);
    k_logits<<<NCHUNK, 256, SMEM_LOGITS>>>(inputs);
    k_out<<<dim3(ROWS / 128, 4), 256>>>(inputs, (float*)d_out);
}

// round 9
// speedup vs baseline: 1.4688x; 1.4688x over previous
#include <cuda_runtime.h>
#include <cuda_bf16.h>
#include <cstdint>

#define BATCH 16
#define NTOK  4096
#define CDIM  512
#define JDIM  64
#define ROWS  (BATCH*NTOK)   // 65536
#define NCHUNK 256           // 256-row softmax chunks (16 per batch)

// ---------- scratch (device globals; no runtime allocation) ----------
__device__ __nv_bfloat16 g_Wbf[JDIM*CDIM];   // fused w1@m0, [j][c]
__device__ float         g_blog[JDIM];       // b1@m0
__device__ __nv_bfloat16 g_Mbf[CDIM*JDIM];   // fused m1@w2, [c][j]
__device__ float         g_bns[CDIM], g_bnt[CDIM];
// logits, bf16, MMA-fragment order: [row/32 block][lane][32 u32]
__device__ uint32_t      g_logbf[2048*32*32];            // 8 MiB
__device__ float         g_pmax[NCHUNK*JDIM], g_psum[NCHUNK*JDIM];

// ---------- helpers ----------
__device__ __forceinline__ uint32_t packbf(float x, float y) {
    __nv_bfloat162 h = __floats2bfloat162_rn(x, y);
    return *reinterpret_cast<uint32_t*>(&h);
}
__device__ __forceinline__ float rt_bf(float x) {
    return __bfloat162float(__float2bfloat16_rn(x));
}
__device__ __forceinline__ void mma16816(float* c, const uint32_t* a, const uint32_t* b) {
    asm volatile(
        "mma.sync.aligned.m16n8k16.row.col.f32.bf16.bf16.f32 "
        "{%0,%1,%2,%3},{%4,%5,%6,%7},{%8,%9},{%0,%1,%2,%3};"
        : "+f"(c[0]), "+f"(c[1]), "+f"(c[2]), "+f"(c[3])
        : "r"(a[0]), "r"(a[1]), "r"(a[2]), "r"(a[3]), "r"(b[0]), "r"(b[1]));
}

// ---------- K0: fold weights, split-K over 4 slices of 128 ----------
__global__ __launch_bounds__(256) void kf_fold(const float* __restrict__ w1, const float* __restrict__ b1,
                       const float* __restrict__ m0, const float* __restrict__ m1,
                       const float* __restrict__ w2, const float* __restrict__ gamma,
                       const float* __restrict__ beta, const float* __restrict__ bmean,
                       const float* __restrict__ bvar) {
    __shared__ float red[4][64];
    int blk = blockIdx.x, tid = threadIdx.x;
    int ks = tid >> 6, lx = tid & 63;

    if (blk < 512) {
        int c = blk;
        const float* w1r = w1 + (size_t)c*CDIM + ks*128;
        const float* m0c = m0 + (size_t)(ks*128)*JDIM + lx;
        float a0=0.f, a1=0.f, a2=0.f, a3=0.f;
        #pragma unroll 8
        for (int q = 0; q < 128; q += 4) {
            a0 = fmaf(w1r[q],   m0c[(q  )*JDIM], a0);
            a1 = fmaf(w1r[q+1], m0c[(q+1)*JDIM], a1);
            a2 = fmaf(w1r[q+2], m0c[(q+2)*JDIM], a2);
            a3 = fmaf(w1r[q+3], m0c[(q+3)*JDIM], a3);
        }
        red[ks][lx] = (a0 + a1) + (a2 + a3);
        __syncthreads();
        if (tid < 64)
            g_Wbf[tid*CDIM + c] = __float2bfloat16_rn(
                (red[0][tid] + red[1][tid]) + (red[2][tid] + red[3][tid]));
    } else if (blk < 1024) {
        int i = blk - 512;
        int j = i >> 3, cb = i & 7;
        int c = cb*64 + lx;
        const float* m1r = m1 + (size_t)j*CDIM + ks*128;
        const float* w2c = w2 + (size_t)(ks*128)*CDIM + c;
        float a0=0.f, a1=0.f, a2=0.f, a3=0.f;
        #pragma unroll 8
        for (int q = 0; q < 128; q += 4) {
            a0 = fmaf(m1r[q],   w2c[(q  )*CDIM], a0);
            a1 = fmaf(m1r[q+1], w2c[(q+1)*CDIM], a1);
            a2 = fmaf(m1r[q+2], w2c[(q+2)*CDIM], a2);
            a3 = fmaf(m1r[q+3], w2c[(q+3)*CDIM], a3);
        }
        red[ks][lx] = (a0 + a1) + (a2 + a3);
        __syncthreads();
        if (tid < 64)
            g_Mbf[(cb*64 + tid)*JDIM + j] = __float2bfloat16_rn(
                (red[0][tid] + red[1][tid]) + (red[2][tid] + red[3][tid]));
    } else if (blk == 1024) {
        for (int c = tid; c < CDIM; c += 256) {
            float s = gamma[c] * rsqrtf(bvar[c] + 1e-3f);
            g_bns[c] = s;
            g_bnt[c] = beta[c] - bmean[c] * s;
        }
    } else {
        const float* b1r = b1 + ks*128;
        const float* m0c = m0 + (size_t)(ks*128)*JDIM + lx;
        float a0=0.f, a1=0.f, a2=0.f, a3=0.f;
        #pragma unroll 8
        for (int q = 0; q < 128; q += 4) {
            a0 = fmaf(b1r[q],   m0c[(q  )*JDIM], a0);
            a1 = fmaf(b1r[q+1], m0c[(q+1)*JDIM], a1);
            a2 = fmaf(b1r[q+2], m0c[(q+2)*JDIM], a2);
            a3 = fmaf(b1r[q+3], m0c[(q+3)*JDIM], a3);
        }
        red[ks][lx] = (a0 + a1) + (a2 + a3);
        __syncthreads();
        if (tid < 64)
            g_blog[tid] = (red[0][tid] + red[1][tid]) + (red[2][tid] + red[3][tid]);
    }
}

// ---------- K1: logits = inputs @ W + blog; float4 A loads; fused stats ----------
// A loads: one float4 per row (natural cols kk+4qc..+3) fed as (k-low, k-high)
// logical slots; B smem words {2qc, 2qc+1} supply the same natural columns.
#define SMEM_LOGITS (64*260*4 + 64*4 + 8*64*4 + 64*4)   // 69120 B

__global__ __launch_bounds__(256) void kl_f4(const float* __restrict__ in) {
    extern __shared__ __align__(16) unsigned char dyn_smem[];
    uint32_t* sw32  = reinterpret_cast<uint32_t*>(dyn_smem);          // [64][260] u32
    float*    sblog = reinterpret_cast<float*>(dyn_smem + 64*260*4);  // [64]
    float*    s_red = sblog + 64;                                     // [8][64]
    float*    s_cmx = s_red + 8*64;                                   // [64]

    int tid = threadIdx.x;
    const uint32_t* gw = reinterpret_cast<const uint32_t*>(g_Wbf); // 256 words/row
    for (int i = tid; i < 64*256; i += 256) {
        int j = i >> 8, w = i & 255;
        sw32[j*260 + w] = gw[i];
    }
    if (tid < JDIM) sblog[tid] = g_blog[tid];
    __syncthreads();

    int warp = tid >> 5, lane = tid & 31;
    int qr = lane >> 2, qc = lane & 3;
    int rowbase = blockIdx.x * 256 + warp * 32;

    float acc[2][8][4];
    #pragma unroll
    for (int nt = 0; nt < 8; nt++) {
        float b0 = sblog[nt*8 + qc*2], b1v = sblog[nt*8 + qc*2 + 1];
        #pragma unroll
        for (int s = 0; s < 2; s++) {
            acc[s][nt][0] = b0; acc[s][nt][1] = b1v;
            acc[s][nt][2] = b0; acc[s][nt][3] = b1v;
        }
    }

    const float* abase = in + (size_t)(rowbase + qr) * CDIM + qc*4;

    #pragma unroll 2
    for (int kk = 0; kk < 512; kk += 16) {
        uint32_t a[2][4];
        #pragma unroll
        for (int s = 0; s < 2; s++) {
            const float* p = abase + s*16*CDIM + kk;
            float4 f0 = *reinterpret_cast<const float4*>(p);
            float4 f1 = *reinterpret_cast<const float4*>(p + 8*CDIM);
            a[s][0] = packbf(f0.x, f0.y);   // row qr,   logical k-low
            a[s][1] = packbf(f1.x, f1.y);   // row qr+8, logical k-low
            a[s][2] = packbf(f0.z, f0.w);   // row qr,   logical k-high
            a[s][3] = packbf(f1.z, f1.w);   // row qr+8, logical k-high
        }
        int bofs = (kk >> 1) + qc*2;
        #pragma unroll
        for (int nt = 0; nt < 8; nt++) {
            int n = nt*8 + qr;
            uint32_t b[2];
            b[0] = sw32[n*260 + bofs];       // natural cols 4qc, 4qc+1
            b[1] = sw32[n*260 + bofs + 1];   // natural cols 4qc+2, 4qc+3
            mma16816(acc[0][nt], a[0], b);
            mma16816(acc[1][nt], a[1], b);
        }
    }

    // ---- store logits in bf16 fragment order: 128B contiguous per lane ----
    {
        uint32_t vals[32];
        #pragma unroll
        for (int t = 0; t < 4; t++)
            #pragma unroll
            for (int s = 0; s < 2; s++) {
                int i0 = t*8 + s*4;
                vals[i0+0] = packbf(acc[s][2*t  ][0], acc[s][2*t  ][1]);
                vals[i0+1] = packbf(acc[s][2*t  ][2], acc[s][2*t  ][3]);
                vals[i0+2] = packbf(acc[s][2*t+1][0], acc[s][2*t+1][1]);
                vals[i0+3] = packbf(acc[s][2*t+1][2], acc[s][2*t+1][3]);
            }
        uint4* dst = reinterpret_cast<uint4*>(
            g_logbf + ((size_t)(blockIdx.x*8 + warp))*1024 + lane*32);
        #pragma unroll
        for (int v = 0; v < 8; v++)
            dst[v] = *reinterpret_cast<uint4*>(&vals[v*4]);
    }

    // ---- fused softmax stats over this CTA's 256 rows (bf16-rounded) ----
    #pragma unroll
    for (int nt = 0; nt < 8; nt++) {
        #pragma unroll
        for (int h = 0; h < 2; h++) {
            float v = fmaxf(fmaxf(rt_bf(acc[0][nt][h]), rt_bf(acc[0][nt][h+2])),
                            fmaxf(rt_bf(acc[1][nt][h]), rt_bf(acc[1][nt][h+2])));
            v = fmaxf(v, __shfl_xor_sync(0xffffffffu, v, 4));
            v = fmaxf(v, __shfl_xor_sync(0xffffffffu, v, 8));
            v = fmaxf(v, __shfl_xor_sync(0xffffffffu, v, 16));
            if (lane < 4) s_red[warp*64 + nt*8 + qc*2 + h] = v;
        }
    }
    __syncthreads();
    if (tid < 64) {
        float m = s_red[tid];
        #pragma unroll
        for (int w = 1; w < 8; w++) m = fmaxf(m, s_red[w*64 + tid]);
        s_cmx[tid] = m;
    }
    __syncthreads();
    #pragma unroll
    for (int nt = 0; nt < 8; nt++) {
        #pragma unroll
        for (int h = 0; h < 2; h++) {
            float cm = s_cmx[nt*8 + qc*2 + h];
            float v = __expf(rt_bf(acc[0][nt][h]) - cm) + __expf(rt_bf(acc[0][nt][h+2]) - cm)
                    + __expf(rt_bf(acc[1][nt][h]) - cm) + __expf(rt_bf(acc[1][nt][h+2]) - cm);
            v += __shfl_xor_sync(0xffffffffu, v, 4);
            v += __shfl_xor_sync(0xffffffffu, v, 8);
            v += __shfl_xor_sync(0xffffffffu, v, 16);
            if (lane < 4) s_red[warp*64 + nt*8 + qc*2 + h] = v;
        }
    }
    __syncthreads();
    if (tid < 64) {
        float s = 0.f;
        #pragma unroll
        for (int w = 0; w < 8; w++) s += s_red[w*64 + tid];
        g_pmax[blockIdx.x*JDIM + tid] = s_cmx[tid];
        g_psum[blockIdx.x*JDIM + tid] = s;
    }
}

// ---------- K2: out = relu( BN( (exp(logits-max)*inv) @ M ) + inputs ) ----------
__global__ __launch_bounds__(256) void ko_gemm(const float* __restrict__ in,
                                               float* __restrict__ out) {
    __shared__ __align__(16) __nv_bfloat16 sM[128 * 72];
    __shared__ float s_s[128], s_t[128], s_mx[64], s_iv[64];

    int tid = threadIdx.x;
    int mt = blockIdx.x, nt4 = blockIdx.y;
    int cbase = nt4 * 128;
    int b = mt >> 5;

    uint32_t* sm32 = reinterpret_cast<uint32_t*>(sM);
    const uint32_t* gm = reinterpret_cast<const uint32_t*>(g_Mbf) + cbase*32;
    for (int i = tid; i < 128*32; i += 256) {
        int c = i >> 5, w = i & 31;
        sm32[c*36 + w] = gm[i];
    }
    if (tid < 128) { s_s[tid] = g_bns[cbase + tid]; s_t[tid] = g_bnt[cbase + tid]; }
    if (tid < 64) {
        float pm[16];
        float gmx = -1e30f;
        #pragma unroll
        for (int ch = 0; ch < 16; ch++) {
            pm[ch] = g_pmax[(b*16 + ch)*JDIM + tid];
            gmx = fmaxf(gmx, pm[ch]);
        }
        float Z = 0.f;
        #pragma unroll
        for (int ch = 0; ch < 16; ch++)
            Z += g_psum[(b*16 + ch)*JDIM + tid] * __expf(pm[ch] - gmx);
        s_mx[tid] = gmx;
        s_iv[tid] = 1.f / (Z * (1.f + 1e-9f));
    }
    __syncthreads();

    int warp = tid >> 5, lane = tid & 31;
    int qr = lane >> 2, qc = lane & 3;
    int wm = warp & 3, wn = warp >> 2;
    int rowbase = mt*128 + wm*32;

    float acc[2][8][4];
    #pragma unroll
    for (int s = 0; s < 2; s++)
        #pragma unroll
        for (int nt = 0; nt < 8; nt++)
            #pragma unroll
            for (int r = 0; r < 4; r++) acc[s][nt][r] = 0.f;

    const uint4* lgb = reinterpret_cast<const uint4*>(
        g_logbf + ((size_t)(mt*4 + wm))*1024 + lane*32);

    #pragma unroll
    for (int t = 0; t < 4; t++) {
        int jj = t * 16;
        int j0 = jj + qc*2;
        float mA = s_mx[j0],   mB = s_mx[j0+1], iA = s_iv[j0],   iB = s_iv[j0+1];
        float mC = s_mx[j0+8], mD = s_mx[j0+9], iC = s_iv[j0+8], iD = s_iv[j0+9];
        uint32_t a[2][4];
        #pragma unroll
        for (int s = 0; s < 2; s++) {
            uint4 v = lgb[t*2 + s];
            float2 f0 = __bfloat1622float2(*reinterpret_cast<__nv_bfloat162*>(&v.x));
            float2 f1 = __bfloat1622float2(*reinterpret_cast<__nv_bfloat162*>(&v.y));
            float2 f2 = __bfloat1622float2(*reinterpret_cast<__nv_bfloat162*>(&v.z));
            float2 f3 = __bfloat1622float2(*reinterpret_cast<__nv_bfloat162*>(&v.w));
            a[s][0] = packbf(__expf(f0.x - mA)*iA, __expf(f0.y - mB)*iB);
            a[s][1] = packbf(__expf(f1.x - mA)*iA, __expf(f1.y - mB)*iB);
            a[s][2] = packbf(__expf(f2.x - mC)*iC, __expf(f2.y - mD)*iD);
            a[s][3] = packbf(__expf(f3.x - mC)*iC, __expf(f3.y - mD)*iD);
        }
        int bofs = (jj >> 1) + qc;
        #pragma unroll
        for (int nt = 0; nt < 8; nt++) {
            int cl = wn*64 + nt*8 + qr;
            uint32_t bb[2] = { sm32[cl*36 + bofs], sm32[cl*36 + bofs + 4] };
            mma16816(acc[0][nt], a[0], bb);
            mma16816(acc[1][nt], a[1], bb);
        }
    }

    #pragma unroll
    for (int s = 0; s < 2; s++)
        #pragma unroll
        for (int nt = 0; nt < 8; nt++) {
            int row = rowbase + s*16 + qr;
            int cl  = wn*64 + nt*8 + qc*2;
            int col = cbase + cl;
            float2 r0 = *reinterpret_cast<const float2*>(&in[(size_t)row*CDIM + col]);
            float2 r1 = *reinterpret_cast<const float2*>(&in[(size_t)(row + 8)*CDIM + col]);
            float2 o0, o1;
            o0.x = fmaxf(fmaf(acc[s][nt][0], s_s[cl],   s_t[cl])   + r0.x, 0.f);
            o0.y = fmaxf(fmaf(acc[s][nt][1], s_s[cl+1], s_t[cl+1]) + r0.y, 0.f);
            o1.x = fmaxf(fmaf(acc[s][nt][2], s_s[cl],   s_t[cl])   + r1.x, 0.f);
            o1.y = fmaxf(fmaf(acc[s][nt][3], s_s[cl+1], s_t[cl+1]) + r1.y, 0.f);
            *reinterpret_cast<float2*>(&out[(size_t)row*CDIM + col]) = o0;
            *reinterpret_cast<float2*>(&out[(size_t)(row + 8)*CDIM + col]) = o1;
        }
}

// ---------- launch ----------
extern "C" void kernel_launch(void* const* d_in, const int* in_sizes, int n_in,
                              void* d_out, int out_size) {
    (void)in_sizes; (void)n_in; (void)out_size;
    const float* inputs = (const float*)d_in[0];
    const float* w1     = (const float*)d_in[1];
    const float* b1     = (const float*)d_in[2];
    const float* m0     = (const float*)d_in[3];
    const float* m1     = (const float*)d_in[4];
    const float* w2     = (const float*)d_in[5];
    const float* gamma  = (const float*)d_in[6];
    const float* beta   = (const float*)d_in[7];
    const float* bmean  = (const float*)d_in[8];
    const float* bvar   = (const float*)d_in[9];

    cudaFuncSetAttribute(kl_f4, cudaFuncAttributeMaxDynamicSharedMemorySize,
                         SMEM_LOGITS);

    kf_fold<<<1026, 256>>>(w1, b1, m0, m1, w2, gamma, beta, bmean, bvar);
    kl_f4<<<NCHUNK, 256, SMEM_LOGITS>>>(inputs);
    ko_gemm<<<dim3(ROWS / 128, 4), 256>>>(inputs, (float*)d_out);
}